// round 13
// baseline (speedup 1.0000x reference)
#include <cuda_runtime.h>
#include <cuda_fp16.h>
#include <float.h>

#define KDIM 256
#define NITER 50
#define NCONS 512
#define NTH 544
#define BPC 4
#define NBUF 5
#define NCHUNK 16                // chunks per batch
#define CHUNK_BYTES 16384        // 16 rows x 256 fp32
#define CHUNK_FLOATS 4096

// Shared memory layout (bytes) — total 215936, under 232448 opt-in cap
#define CS_OFF   0               // 131072: 256 rows x 64 uint2 (fp16), XOR-swizzled
#define STG_OFF  131072          // 81920: 5 x 16KB fp32 staging ring
#define FS_OFF   212992          // 1024: f = 0.5*scores
#define GV_OFF   214016          // 1024: row sums
#define WS_OFF   215040          // 64: 16 warp partial sums
#define WT_OFF   215104          // 64
#define WM_OFF   215168          // 64
#define CN_OFF   215232          // 32: A, Bc, eps, Cc
#define GT_OFF   215264          // 400: 50 x float2
#define MB_OFF   215680          // 40: 5 data mbarriers
#define MC_OFF   215720          // 40: 5 consumption mbarriers
#define FL_OFF   215760          // 16
#define RB_OFF   215776          // 96: 17 floats reduce scratch
#define SMEM_BYTES 215936

__device__ float g_scratch[1024];
__device__ unsigned int g_count = 0;

__device__ __forceinline__ float ex2f(float x) {
    float y;
    asm("ex2.approx.ftz.f32 %0, %1;" : "=f"(y) : "f"(x));
    return y;
}
__device__ __forceinline__ void mbar_init(unsigned mbar, unsigned cnt) {
    asm volatile("mbarrier.init.shared::cta.b64 [%0], %1;" :: "r"(mbar), "r"(cnt) : "memory");
}
__device__ __forceinline__ void mbar_expect(unsigned mbar, unsigned bytes) {
    asm volatile("mbarrier.arrive.expect_tx.shared::cta.b64 _, [%0], %1;"
                 :: "r"(mbar), "r"(bytes) : "memory");
}
__device__ __forceinline__ void mbar_arrive(unsigned mbar) {
    asm volatile("mbarrier.arrive.shared::cta.b64 _, [%0];" :: "r"(mbar) : "memory");
}
__device__ __forceinline__ void mbar_wait(unsigned mbar, unsigned phase) {
    asm volatile(
        "{\n\t"
        ".reg .pred P;\n\t"
        "LW_%=:\n\t"
        "mbarrier.try_wait.parity.shared::cta.b64 P, [%0], %1;\n\t"
        "@!P bra LW_%=;\n\t"
        "}\n"
        :: "r"(mbar), "r"(phase) : "memory");
}
__device__ __forceinline__ void tma_1d(unsigned dst, const void* src, unsigned bytes, unsigned mbar) {
    asm volatile(
        "cp.async.bulk.shared::cluster.global.mbarrier::complete_tx::bytes [%0], [%1], %2, [%3];"
        :: "r"(dst), "l"(src), "r"(bytes), "r"(mbar) : "memory");
}

// Frank-Wolfe: single warp, packed-key argmin (1 REDUX/iter), PRMT half select,
// conflict-free LDS.64 column gather.
__device__ __forceinline__ void run_fw(const uint2* __restrict__ Cs, const float* __restrict__ gv,
                                       const float* __restrict__ cons, const float2* __restrict__ gtab,
                                       const float* __restrict__ scores, const int* __restrict__ targets,
                                       int b, int lane)
{
    float gr[8], al[8];
    #pragma unroll
    for (int m = 0; m < 8; m++) { gr[m] = gv[lane + 32 * m]; al[m] = 0.00390625f; }
    for (int it = 0; it < NITER; it++) {
        float2 gg = gtab[it];
        unsigned key = 0xffffffffu;
        #pragma unroll
        for (int m = 0; m < 8; m++)
            key = min(key, (__float_as_uint(gr[m]) & 0xffffff00u) | (unsigned)(lane + 32 * m));
        unsigned kmin = __reduce_min_sync(0xffffffffu, key);
        unsigned idx = kmin & 0xffu;
        unsigned pw  = (idx >> 2) ^ (unsigned)lane;
        unsigned ctl = (idx & 3u) * 0x22u + 0x10u;
        #pragma unroll
        for (int m = 0; m < 8; m++) {
            unsigned row = (unsigned)lane + 32u * m;
            uint2 u = Cs[row * 64u + pw];
            unsigned hw = __byte_perm(u.x, u.y, ctl);
            float colv = __half2float(__ushort_as_half((unsigned short)hw));
            gr[m] = fmaf(gg.x, colv, gg.y * gr[m]);
            al[m] = fmaf(gg.y, al[m], (row == idx) ? gg.x : 0.0f);
        }
    }
    float dot = 0.f;
    #pragma unroll
    for (int m = 0; m < 8; m++) dot = fmaf(al[m], gr[m], dot);
    #pragma unroll
    for (int o = 16; o; o >>= 1) dot += __shfl_xor_sync(0xffffffffu, dot, o);
    if (lane == 0) {
        float conj = cons[3] - cons[2] * __logf(dot);
        g_scratch[b] = conj - scores[b * KDIM + targets[b]];
    }
}

extern "C" __global__ void __launch_bounds__(NTH, 1)
cacis_fused(const float* __restrict__ scores, const int* __restrict__ targets,
            const float* __restrict__ C, float* __restrict__ out, int B)
{
    extern __shared__ unsigned char smraw[];
    uint2*  Cs   = (uint2*)(smraw + CS_OFF);
    float*  fs   = (float*)(smraw + FS_OFF);
    float*  gv   = (float*)(smraw + GV_OFF);
    float*  wsum = (float*)(smraw + WS_OFF);
    float*  wtr  = (float*)(smraw + WT_OFF);
    float*  wmin = (float*)(smraw + WM_OFF);
    float*  cons = (float*)(smraw + CN_OFF);
    float2* gtab = (float2*)(smraw + GT_OFF);
    int*    flg  = (int*)(smraw + FL_OFF);
    float*  rbuf = (float*)(smraw + RB_OFF);
    const float4* fs4 = (const float4*)fs;

    const unsigned smem_base = (unsigned)__cvta_generic_to_shared(smraw);
    const unsigned stgB = smem_base + STG_OFF;
    const unsigned mbB  = smem_base + MB_OFF;   // data barriers (count 1, tx)
    const unsigned mcB  = smem_base + MC_OFF;   // consumption barriers (count 16)

    const int t = threadIdx.x, lane = t & 31, wid = t >> 5;
    const int b0 = blockIdx.x * BPC;
    const int nb = min(BPC, B - b0);
    const int total = nb * NCHUNK;
    const float* Cbase = C + (size_t)b0 * (KDIM * KDIM);

    // ---- prologue ----
    if (t == 0) {
        #pragma unroll
        for (int i = 0; i < NBUF; i++) { mbar_init(mbB + 8u * i, 1); mbar_init(mcB + 8u * i, 16); }
    }
    if (t < KDIM) fs[t] = 0.5f * scores[b0 * KDIM + t];
    if (t < NITER) { float g = 2.0f / (float)(t + 2); gtab[t] = make_float2(g, 1.0f - g); }
    __syncthreads();
    if (t == NCONS) {            // producer lane issues initial NBUF chunks
        #pragma unroll
        for (int s = 0; s < NBUF; s++) {
            if (s < total) {
                mbar_expect(mbB + 8u * s, CHUNK_BYTES);
                tma_1d(stgB + s * CHUNK_BYTES, Cbase + (size_t)s * CHUNK_FLOATS, CHUNK_BYTES, mbB + 8u * s);
            }
        }
    }

    for (int k = 0; k < nb; k++) {
        // ========== convert: barrier-free producer/consumer over 16 chunks ==========
        if (t < NCONS) {
            float psum = 0.f, ptrc = 0.f, pmin = FLT_MAX;
            const int rl = wid;                      // warp owns one row per chunk
            const float4 fj0 = fs4[lane];
            const float4 fj1 = fs4[lane + 32];
            const int c40 = lane, c41 = lane + 32;
            #pragma unroll
            for (int c = 0; c < NCHUNK; c++) {
                const int gc = k * NCHUNK + c;
                const int bi = gc % NBUF;
                mbar_wait(mbB + 8u * bi, (unsigned)((gc / NBUF) & 1));
                const float4* stg = (const float4*)(smraw + STG_OFF + bi * CHUNK_BYTES);
                const int r = c * 16 + rl;
                const float fi = fs[r];
                float4 cc0 = stg[rl * 64 + c40];
                float4 cc1 = stg[rl * 64 + c41];

                float v0 = fminf(fj0.x + cc0.x, fj0.y + cc0.y);
                float v1 = fminf(fj0.z + cc0.z, fj0.w + cc0.w);
                float v2 = fminf(fj1.x + cc1.x, fj1.y + cc1.y);
                float v3 = fminf(fj1.z + cc1.z, fj1.w + cc1.w);
                pmin = fminf(pmin, fi + fminf(fminf(v0, v1), fminf(v2, v3)));
                psum += ((cc0.x + cc0.y) + (cc0.z + cc0.w)) + ((cc1.x + cc1.y) + (cc1.z + cc1.w));
                int d0 = r - 4 * c40;
                if ((unsigned)d0 < 4u)
                    ptrc += (d0 == 0) ? cc0.x : (d0 == 1) ? cc0.y : (d0 == 2) ? cc0.z : cc0.w;
                int d1 = r - 4 * c41;
                if ((unsigned)d1 < 4u)
                    ptrc += (d1 == 0) ? cc1.x : (d1 == 1) ? cc1.y : (d1 == 2) ? cc1.z : cc1.w;

                __half2 h00 = __floats2half2_rn(cc0.x, cc0.y);
                __half2 h01 = __floats2half2_rn(cc0.z, cc0.w);
                __half2 h10 = __floats2half2_rn(cc1.x, cc1.y);
                __half2 h11 = __floats2half2_rn(cc1.z, cc1.w);
                uint2 s0, s1;
                s0.x = *(unsigned*)&h00; s0.y = *(unsigned*)&h01;
                s1.x = *(unsigned*)&h10; s1.y = *(unsigned*)&h11;
                const int sw = r & 31;
                Cs[r * 64 + (c40 ^ sw)] = s0;
                Cs[r * 64 + (c41 ^ sw)] = s1;

                if (lane == 0) mbar_arrive(mcB + 8u * bi);   // this warp done with chunk gc
            }
            #pragma unroll
            for (int o = 16; o; o >>= 1) {
                psum += __shfl_down_sync(0xffffffffu, psum, o);
                ptrc += __shfl_down_sync(0xffffffffu, ptrc, o);
                pmin  = fminf(pmin, __shfl_down_sync(0xffffffffu, pmin, o));
            }
            if (lane == 0) { wsum[wid] = psum; wtr[wid] = ptrc; wmin[wid] = pmin; }
        } else if (t == NCONS) {
            // producer: issue chunks [k*16+NBUF, (k+1)*16+NBUF), each gated on
            // consumption of chunk s-NBUF (same staging slot)
            #pragma unroll
            for (int c = 0; c < NCHUNK; c++) {
                const int s = k * NCHUNK + c + NBUF;
                if (s < total) {
                    const int cc = s - NBUF;
                    mbar_wait(mcB + 8u * (cc % NBUF), (unsigned)((cc / NBUF) & 1));
                    const int bi = s % NBUF;
                    mbar_expect(mbB + 8u * bi, CHUNK_BYTES);
                    tma_1d(stgB + bi * CHUNK_BYTES, Cbase + (size_t)s * CHUNK_FLOATS, CHUNK_BYTES, mbB + 8u * bi);
                }
            }
        }
        __syncthreads();

        if (t == 0) {
            float s = 0.f, tr = 0.f, mn = FLT_MAX;
            #pragma unroll
            for (int w = 0; w < 16; w++) { s += wsum[w]; tr += wtr[w]; mn = fminf(mn, wmin[w]); }
            float eps = fmaxf((s - tr) / 65280.0f, 1e-8f);      // K*K-K
            float k2 = 1.4426950408889634f / eps;               // log2(e)/eps
            cons[0] = -k2;                                      // A
            cons[1] = fmaf(mn, k2, 14.0f);                      // Bc: M' = M * 2^14
            cons[2] = eps;
            cons[3] = fmaf(9.7040605278392342f, eps, mn);       // Cc = mn + 14*ln2*eps
        }
        if (t < KDIM) gv[t] = 0.0f;
        __syncthreads();

        // ========== transform: Cs fp16 C -> fp16 M' = 2^((mn-num)*k + 14), row sums ==========
        if (t < NCONS) {
            const float A = cons[0], Bc = cons[1];
            const int i = t & 255, hh = t >> 8, sw = i & 31;
            uint2* rowp = Cs + i * 64;
            const float fiAB = fmaf(fs[i], A, Bc);
            float rs = 0.f;
            #pragma unroll 8
            for (int ww = hh * 32; ww < hh * 32 + 32; ww++) {
                const int pa = ww ^ sw;
                uint2 uu = rowp[pa];
                float2 c01 = __half22float2(*(__half2*)&uu.x);
                float2 c23 = __half22float2(*(__half2*)&uu.y);
                float4 fj = fs4[ww];
                float m0 = ex2f(fmaf(c01.x, A, fmaf(fj.x, A, fiAB)));
                float m1 = ex2f(fmaf(c01.y, A, fmaf(fj.y, A, fiAB)));
                float m2 = ex2f(fmaf(c23.x, A, fmaf(fj.z, A, fiAB)));
                float m3 = ex2f(fmaf(c23.y, A, fmaf(fj.w, A, fiAB)));
                rs += (m0 + m1) + (m2 + m3);
                __half2 o01 = __floats2half2_rn(m0, m1);
                __half2 o23 = __floats2half2_rn(m2, m3);
                uint2 st;
                st.x = *(unsigned*)&o01;
                st.y = *(unsigned*)&o23;
                rowp[pa] = st;
            }
            atomicAdd(&gv[i], rs);                    // exactly 2 commutative adds per row
        }
        __syncthreads();

        // ========== FW (warp 0) || fs prefetch for next batch (warp 16) ==========
        if (wid == 0) {
            run_fw(Cs, gv, cons, gtab, scores, targets, b0 + k, lane);
        } else if (wid == 16 && k + 1 < nb) {
            #pragma unroll
            for (int i = lane; i < KDIM; i += 32)
                fs[i] = 0.5f * scores[(b0 + k + 1) * KDIM + i];
        }
        __syncthreads();
    }

    // ---- fused cross-CTA reduction: last CTA sums g_scratch in fixed order ----
    if (t == 0) {
        __threadfence();
        unsigned prev = atomicAdd(&g_count, 1u);
        *flg = (prev == gridDim.x - 1) ? 1 : 0;
    }
    __syncthreads();
    if (*flg) {
        if (t == 0) g_count = 0;                      // reset for next graph replay
        __threadfence();
        float s = 0.f;
        for (int i = t; i < B; i += NTH) s += __ldcg(&g_scratch[i]);
        #pragma unroll
        for (int o = 16; o; o >>= 1) s += __shfl_down_sync(0xffffffffu, s, o);
        if (lane == 0) rbuf[wid] = s;
        __syncthreads();
        if (t == 0) {
            float tot = 0.f;
            #pragma unroll
            for (int w = 0; w < 17; w++) tot += rbuf[w];
            out[0] = tot / (float)B;
        }
    }
}

extern "C" void kernel_launch(void* const* d_in, const int* in_sizes, int n_in,
                              void* d_out, int out_size)
{
    const float* scores  = (const float*)d_in[0];
    const int*   targets = (const int*)d_in[1];
    const float* C       = (const float*)d_in[2];
    const int B = in_sizes[1];
    const int grid = (B + BPC - 1) / BPC;

    cudaFuncSetAttribute(cacis_fused, cudaFuncAttributeMaxDynamicSharedMemorySize, SMEM_BYTES);
    cacis_fused<<<grid, NTH, SMEM_BYTES>>>(scores, targets, C, (float*)d_out, B);
}